// round 1
// baseline (speedup 1.0000x reference)
#include <cuda_runtime.h>

#define Bn  16
#define Tn  2048
#define Cn  384
#define DKn 64

// Scratch for projected q, k, v  (16*2048*64 floats = 8 MB each)
__device__ __align__(16) float g_q[Bn * Tn * DKn];
__device__ __align__(16) float g_k[Bn * Tn * DKn];
__device__ __align__(16) float g_v[Bn * Tn * DKn];

// ---------------------------------------------------------------------------
// Fused projection: q/k/v[r][d] = sum_c x[r][c] * W{Q,K,V}[c][d]
// Block: 256 threads, computes a 128-row x 64-col tile for ALL THREE mats.
// ---------------------------------------------------------------------------
__global__ __launch_bounds__(256, 1) void proj_kernel(
    const float* __restrict__ x,
    const float* __restrict__ WQ,
    const float* __restrict__ WK,
    const float* __restrict__ WV)
{
    __shared__ float xs[128][36];      // 36 = pad for banks, 144B row (16B aligned)
    __shared__ float ws[3][32][64];

    const int r0  = blockIdx.x * 128;
    const int tid = threadIdx.x;
    const int tx  = tid & 15;          // col group: cols tx*4 .. tx*4+3
    const int ty  = tid >> 4;          // row group: rows ty*8 .. ty*8+7

    float acc[3][8][4];
#pragma unroll
    for (int m = 0; m < 3; m++)
#pragma unroll
        for (int i = 0; i < 8; i++)
#pragma unroll
            for (int j = 0; j < 4; j++) acc[m][i][j] = 0.f;

    for (int kk = 0; kk < Cn; kk += 32) {
        // load x tile: 128 rows x 32 cols
#pragma unroll
        for (int it = 0; it < 4; it++) {
            int i   = tid + it * 256;
            int row = i >> 3;
            int c4  = (i & 7) << 2;
            float4 v = *(const float4*)(x + (size_t)(r0 + row) * Cn + kk + c4);
            *(float4*)&xs[row][c4] = v;
        }
        // load W tiles: 3 x 32 x 64
#pragma unroll
        for (int it = 0; it < 6; it++) {
            int i   = tid + it * 256;
            int m   = i >> 9;                 // / 512
            int rem = i & 511;
            int row = rem >> 4;
            int c4  = (rem & 15) << 2;
            const float* W = (m == 0) ? WQ : ((m == 1) ? WK : WV);
            *(float4*)&ws[m][row][c4] =
                *(const float4*)(W + (size_t)(kk + row) * DKn + c4);
        }
        __syncthreads();

#pragma unroll 4
        for (int k = 0; k < 32; k++) {
            float4 w0 = *(const float4*)&ws[0][k][tx << 2];
            float4 w1 = *(const float4*)&ws[1][k][tx << 2];
            float4 w2 = *(const float4*)&ws[2][k][tx << 2];
#pragma unroll
            for (int i = 0; i < 8; i++) {
                float xv = xs[(ty << 3) + i][k];
                acc[0][i][0] += xv * w0.x; acc[0][i][1] += xv * w0.y;
                acc[0][i][2] += xv * w0.z; acc[0][i][3] += xv * w0.w;
                acc[1][i][0] += xv * w1.x; acc[1][i][1] += xv * w1.y;
                acc[1][i][2] += xv * w1.z; acc[1][i][3] += xv * w1.w;
                acc[2][i][0] += xv * w2.x; acc[2][i][1] += xv * w2.y;
                acc[2][i][2] += xv * w2.z; acc[2][i][3] += xv * w2.w;
            }
        }
        __syncthreads();
    }

#pragma unroll
    for (int i = 0; i < 8; i++) {
        size_t row = (size_t)(r0 + (ty << 3) + i);
        float4 oq = {acc[0][i][0], acc[0][i][1], acc[0][i][2], acc[0][i][3]};
        float4 ok = {acc[1][i][0], acc[1][i][1], acc[1][i][2], acc[1][i][3]};
        float4 ov = {acc[2][i][0], acc[2][i][1], acc[2][i][2], acc[2][i][3]};
        *(float4*)(g_q + row * DKn + (tx << 2)) = oq;
        *(float4*)(g_k + row * DKn + (tx << 2)) = ok;
        *(float4*)(g_v + row * DKn + (tx << 2)) = ov;
    }
}

// ---------------------------------------------------------------------------
// Causal flash attention: one thread per query row, online softmax.
// Block: 64 threads = 64 query rows. K/V tiles of 64 rows staged in smem.
// ---------------------------------------------------------------------------
#define BM 64
#define BN 64

__global__ __launch_bounds__(64) void attn_kernel(float* __restrict__ out)
{
    __shared__ float Ks[BN][DKn];
    __shared__ float Vs[BN][DKn];

    const int b   = blockIdx.y;
    const int qt  = (Tn / BM - 1) - blockIdx.x;   // heavy tiles first
    const int q0  = qt * BM;
    const int tid = threadIdx.x;
    const int qi  = q0 + tid;

    // load + pre-scale q row (scale = 1/sqrt(64) = 0.125)
    float q[DKn];
    {
        const float* qp = g_q + ((size_t)b * Tn + qi) * DKn;
#pragma unroll
        for (int d = 0; d < DKn; d += 4) {
            float4 v = *(const float4*)(qp + d);
            q[d] = v.x * 0.125f; q[d + 1] = v.y * 0.125f;
            q[d + 2] = v.z * 0.125f; q[d + 3] = v.w * 0.125f;
        }
    }

    float m = -3.4e38f, l = 0.f;
    float acc[DKn];
#pragma unroll
    for (int d = 0; d < DKn; d++) acc[d] = 0.f;

    const int kend = q0 + BM;                     // causal bound (exclusive)
    for (int ks = 0; ks < kend; ks += BN) {
        const float4* kp = (const float4*)(g_k + ((size_t)b * Tn + ks) * DKn);
        const float4* vp = (const float4*)(g_v + ((size_t)b * Tn + ks) * DKn);
#pragma unroll
        for (int it = 0; it < (BN * DKn / 4) / 64; it++) {   // 16 iters
            int i = tid + it * 64;
            ((float4*)&Ks[0][0])[i] = kp[i];
            ((float4*)&Vs[0][0])[i] = vp[i];
        }
        __syncthreads();

        const int jmax = min(BN, qi - ks + 1);
        for (int j = 0; j < jmax; j++) {
            float s = 0.f;
#pragma unroll
            for (int d = 0; d < DKn; d += 4) {
                float4 k4 = *(const float4*)&Ks[j][d];
                s += q[d] * k4.x + q[d + 1] * k4.y
                   + q[d + 2] * k4.z + q[d + 3] * k4.w;
            }
            if (s > m) {                          // lazy rescale on new max
                float corr = __expf(m - s);
                l *= corr;
#pragma unroll
                for (int d = 0; d < DKn; d++) acc[d] *= corr;
                m = s;
            }
            float p = __expf(s - m);
            l += p;
#pragma unroll
            for (int d = 0; d < DKn; d += 4) {
                float4 v4 = *(const float4*)&Vs[j][d];
                acc[d]     += p * v4.x; acc[d + 1] += p * v4.y;
                acc[d + 2] += p * v4.z; acc[d + 3] += p * v4.w;
            }
        }
        __syncthreads();
    }

    const float inv = 1.f / l;
    float* op = out + ((size_t)b * Tn + qi) * DKn;
#pragma unroll
    for (int d = 0; d < DKn; d += 4) {
        float4 o = {acc[d] * inv, acc[d + 1] * inv,
                    acc[d + 2] * inv, acc[d + 3] * inv};
        *(float4*)(op + d) = o;
    }
}

// ---------------------------------------------------------------------------
extern "C" void kernel_launch(void* const* d_in, const int* in_sizes, int n_in,
                              void* d_out, int out_size)
{
    const float* x  = (const float*)d_in[0];
    const float* WQ = (const float*)d_in[1];
    const float* WK = (const float*)d_in[2];
    const float* WV = (const float*)d_in[3];
    float* out = (float*)d_out;

    proj_kernel<<<(Bn * Tn) / 128, 256>>>(x, WQ, WK, WV);
    attn_kernel<<<dim3(Tn / BM, Bn), BM>>>(out);
}

// round 3
// speedup vs baseline: 3.1364x; 3.1364x over previous
#include <cuda_runtime.h>
#include <cuda_bf16.h>
#include <cstdint>

#define Bn  16
#define Tn  2048
#define Cn  384
#define DKn 64

// Pre-split bf16 operands produced by proj kernel
__device__ __align__(16) __nv_bfloat16 g_qhi [Bn * Tn * DKn];
__device__ __align__(16) __nv_bfloat16 g_qlo [Bn * Tn * DKn];
__device__ __align__(16) __nv_bfloat16 g_khi [Bn * Tn * DKn];
__device__ __align__(16) __nv_bfloat16 g_klo [Bn * Tn * DKn];
__device__ __align__(16) __nv_bfloat16 g_vthi[Bn * DKn * Tn];   // [b][d][t]
__device__ __align__(16) __nv_bfloat16 g_vtlo[Bn * DKn * Tn];

// ===================== helpers =====================
__device__ __forceinline__ uint32_t smem_u32(const void* p) {
    uint32_t a;
    asm("{ .reg .u64 t; cvta.to.shared.u64 t, %1; cvt.u32.u64 %0, t; }" : "=r"(a) : "l"(p));
    return a;
}
// pack two f32 -> bf16x2 (e0 in low half)
__device__ __forceinline__ uint32_t pack2(float e0, float e1) {
    uint32_t r;
    asm("cvt.rn.bf16x2.f32 %0, %1, %2;" : "=r"(r) : "f"(e1), "f"(e0));
    return r;
}
__device__ __forceinline__ void split2(float e0, float e1, uint32_t& hi, uint32_t& lo) {
    hi = pack2(e0, e1);
    float h0 = __uint_as_float(hi << 16);
    float h1 = __uint_as_float(hi & 0xffff0000u);
    lo = pack2(e0 - h0, e1 - h1);
}
__device__ __forceinline__ void ldsm4(uint32_t r[4], uint32_t addr) {
    asm volatile("ldmatrix.sync.aligned.m8n8.x4.shared.b16 {%0,%1,%2,%3}, [%4];"
        : "=r"(r[0]), "=r"(r[1]), "=r"(r[2]), "=r"(r[3]) : "r"(addr));
}
__device__ __forceinline__ void mma16816(float c[4], const uint32_t a[4],
                                         uint32_t b0, uint32_t b1) {
    asm volatile(
        "mma.sync.aligned.m16n8k16.row.col.f32.bf16.bf16.f32 "
        "{%0,%1,%2,%3},{%4,%5,%6,%7},{%8,%9},{%0,%1,%2,%3};"
        : "+f"(c[0]), "+f"(c[1]), "+f"(c[2]), "+f"(c[3])
        : "r"(a[0]), "r"(a[1]), "r"(a[2]), "r"(a[3]), "r"(b0), "r"(b1));
}
#define STS128(a, v) \
    asm volatile("st.shared.v4.b32 [%0], {%1,%2,%3,%4};" \
        :: "r"(a), "r"((v).x), "r"((v).y), "r"((v).z), "r"((v).w) : "memory")

// ===================== projection =====================
__global__ __launch_bounds__(256, 1) void proj_kernel(
    const float* __restrict__ x,
    const float* __restrict__ WQ,
    const float* __restrict__ WK,
    const float* __restrict__ WV)
{
    __shared__ __align__(16) float sbuf[10752];
    float (*xs)[36]     = (float(*)[36])sbuf;
    float (*ws)[32][64] = (float(*)[32][64])(sbuf + 4608);
    float (*vt)[65]     = (float(*)[65])sbuf;      // overlay after main loop

    const int r0  = blockIdx.x * 128;
    const int tid = threadIdx.x;
    const int tx  = tid & 15;
    const int ty  = tid >> 4;

    float acc[3][8][4];
#pragma unroll
    for (int m = 0; m < 3; m++)
#pragma unroll
        for (int i = 0; i < 8; i++)
#pragma unroll
            for (int j = 0; j < 4; j++) acc[m][i][j] = 0.f;

    for (int kk = 0; kk < Cn; kk += 32) {
#pragma unroll
        for (int it = 0; it < 4; it++) {
            int i = tid + it * 256;
            int rr = i >> 3, c4 = (i & 7) << 2;
            *(float4*)&xs[rr][c4] = *(const float4*)(x + (size_t)(r0 + rr) * Cn + kk + c4);
        }
#pragma unroll
        for (int it = 0; it < 6; it++) {
            int i = tid + it * 256;
            int m = i >> 9, rem = i & 511;
            int rr = rem >> 4, c4 = (rem & 15) << 2;
            const float* W = (m == 0) ? WQ : ((m == 1) ? WK : WV);
            *(float4*)&ws[m][rr][c4] = *(const float4*)(W + (size_t)(kk + rr) * DKn + c4);
        }
        __syncthreads();
#pragma unroll 4
        for (int k = 0; k < 32; k++) {
            float4 w0 = *(const float4*)&ws[0][k][tx << 2];
            float4 w1 = *(const float4*)&ws[1][k][tx << 2];
            float4 w2 = *(const float4*)&ws[2][k][tx << 2];
#pragma unroll
            for (int i = 0; i < 8; i++) {
                float xv = xs[(ty << 3) + i][k];
                acc[0][i][0] += xv * w0.x; acc[0][i][1] += xv * w0.y;
                acc[0][i][2] += xv * w0.z; acc[0][i][3] += xv * w0.w;
                acc[1][i][0] += xv * w1.x; acc[1][i][1] += xv * w1.y;
                acc[1][i][2] += xv * w1.z; acc[1][i][3] += xv * w1.w;
                acc[2][i][0] += xv * w2.x; acc[2][i][1] += xv * w2.y;
                acc[2][i][2] += xv * w2.z; acc[2][i][3] += xv * w2.w;
            }
        }
        __syncthreads();
    }

    // Q (x0.125) and K: split to bf16 hi/lo, direct store
#pragma unroll
    for (int i = 0; i < 8; i++) {
        size_t rr = (size_t)(r0 + (ty << 3) + i);
        size_t off = rr * DKn + (tx << 2);
        uint32_t h0, h1, l0, l1;
        split2(acc[0][i][0] * 0.125f, acc[0][i][1] * 0.125f, h0, l0);
        split2(acc[0][i][2] * 0.125f, acc[0][i][3] * 0.125f, h1, l1);
        *(uint2*)(g_qhi + off) = make_uint2(h0, h1);
        *(uint2*)(g_qlo + off) = make_uint2(l0, l1);
        split2(acc[1][i][0], acc[1][i][1], h0, l0);
        split2(acc[1][i][2], acc[1][i][3], h1, l1);
        *(uint2*)(g_khi + off) = make_uint2(h0, h1);
        *(uint2*)(g_klo + off) = make_uint2(l0, l1);
        // V staged fp32 to smem for transpose
#pragma unroll
        for (int j = 0; j < 4; j++) vt[(ty << 3) + i][(tx << 2) + j] = acc[2][i][j];
    }
    __syncthreads();

    const int b  = r0 >> 11;
    const int t0 = r0 & 2047;
    const int d  = tid >> 2;
    const int tq = (tid & 3) << 5;
#pragma unroll
    for (int g = 0; g < 8; g++) {
        int tl = tq + g * 4;
        float v0 = vt[tl][d], v1 = vt[tl + 1][d], v2 = vt[tl + 2][d], v3 = vt[tl + 3][d];
        uint32_t h0, h1, l0, l1;
        split2(v0, v1, h0, l0);
        split2(v2, v3, h1, l1);
        size_t off = ((size_t)(b * DKn + d) << 11) + t0 + tl;
        *(uint2*)(g_vthi + off) = make_uint2(h0, h1);
        *(uint2*)(g_vtlo + off) = make_uint2(l0, l1);
    }
}

// ===================== attention (mma.sync bf16, split precision) =====================
// smem: XOR-swizzled tiles, 128B rows. Offsets from 128-aligned base.
#define QHI_O 0u
#define QLO_O 16384u
#define KHI_O 32768u
#define KLO_O 40960u
#define VHI_O 49152u
#define VLO_O 57344u
#define SMEM_BYTES (65536u + 1024u)

extern __shared__ __align__(16) char dsmem[];

__global__ __launch_bounds__(256, 1) void attn_kernel(float* __restrict__ out)
{
    uint32_t raw = smem_u32(dsmem);
    uint32_t sb  = (raw + 127u) & ~127u;

    const int tid = threadIdx.x;
    const int w   = tid >> 5;
    const int l   = tid & 31;

    const int bx = blockIdx.x;
    const int qt = 15 - (bx >> 4);          // heavy q-tiles first
    const int b  = bx & 15;
    const int q0 = qt << 7;

    // ---- stage Q tiles (bf16 hi/lo), swizzled ----
    {
        const uint4* qh = (const uint4*)(g_qhi + (((size_t)(b * Tn + q0)) << 6));
        const uint4* ql = (const uint4*)(g_qlo + (((size_t)(b * Tn + q0)) << 6));
#pragma unroll
        for (int i = 0; i < 4; i++) {
            int idx = tid + (i << 8);
            int r = idx >> 3, u = idx & 7;
            uint32_t sw = (uint32_t)r * 128u + (uint32_t)((u ^ (r & 7)) << 4);
            uint4 vh = qh[idx], vl = ql[idx];
            STS128(sb + QHI_O + sw, vh);
            STS128(sb + QLO_O + sw, vl);
        }
    }
    __syncthreads();

    // ---- Q fragments (registers, whole loop) ----
    uint32_t qh[4][4], qlr[4][4];
    {
        int arow = (w << 4) + (l & 7) + (((l >> 3) & 1) << 3);
        uint32_t rb = sb + (uint32_t)arow * 128u;
#pragma unroll
        for (int kk = 0; kk < 4; kk++) {
            int u = (kk << 1) + (l >> 4);
            uint32_t sw = (uint32_t)((u ^ (arow & 7)) << 4);
            ldsm4(qh[kk],  rb + QHI_O + sw);
            ldsm4(qlr[kk], rb + QLO_O + sw);
        }
    }

    float m0 = -3.0e38f, m1 = -3.0e38f, ls0 = 0.f, ls1 = 0.f;
    float o[8][4];
#pragma unroll
    for (int i = 0; i < 8; i++)
#pragma unroll
        for (int j = 0; j < 4; j++) o[i][j] = 0.f;

    const int kend  = q0 + 128;
    const int wrow0 = q0 + (w << 4);        // warp's lowest q row

    for (int ks = 0; ks < kend; ks += 64) {
        // ---- stage K / Vt tiles ----
        {
            const uint4* kh = (const uint4*)(g_khi + (((size_t)(b * Tn + ks)) << 6));
            const uint4* kl = (const uint4*)(g_klo + (((size_t)(b * Tn + ks)) << 6));
            const __nv_bfloat16* vhb = g_vthi + (((size_t)(b * DKn)) << 11) + ks;
            const __nv_bfloat16* vlb = g_vtlo + (((size_t)(b * DKn)) << 11) + ks;
#pragma unroll
            for (int i = 0; i < 2; i++) {
                int idx = tid + (i << 8);
                int r = idx >> 3, u = idx & 7;
                uint32_t sw = (uint32_t)r * 128u + (uint32_t)((u ^ (r & 7)) << 4);
                uint4 a = kh[idx], c = kl[idx];
                STS128(sb + KHI_O + sw, a);
                STS128(sb + KLO_O + sw, c);
                uint4 e = *(const uint4*)(vhb + ((size_t)r << 11) + (u << 3));
                uint4 f = *(const uint4*)(vlb + ((size_t)r << 11) + (u << 3));
                STS128(sb + VHI_O + sw, e);
                STS128(sb + VLO_O + sw, f);
            }
        }
        __syncthreads();

        if (ks <= wrow0 + 15) {             // warp has unmasked work
            const int brow = l & 7;
            const int bu   = l >> 3;

            // ---- S = Q K^T (3-term split) ----
            float sc[8][4];
#pragma unroll
            for (int nt = 0; nt < 8; nt++) {
                int row = (nt << 3) + brow;
                uint32_t rb = sb + (uint32_t)row * 128u;
                uint32_t s0 = (uint32_t)((bu       ^ (row & 7)) << 4);
                uint32_t s1 = (uint32_t)(((4 + bu) ^ (row & 7)) << 4);
                uint32_t kh8[8], kl8[8];
                ldsm4(kh8,     rb + KHI_O + s0);
                ldsm4(kh8 + 4, rb + KHI_O + s1);
                ldsm4(kl8,     rb + KLO_O + s0);
                ldsm4(kl8 + 4, rb + KLO_O + s1);
#pragma unroll
                for (int j = 0; j < 4; j++) sc[nt][j] = 0.f;
#pragma unroll
                for (int s = 0; s < 4; s++) {
                    mma16816(sc[nt], qh[s],  kh8[2 * s], kh8[2 * s + 1]);
                    mma16816(sc[nt], qh[s],  kl8[2 * s], kl8[2 * s + 1]);
                    mma16816(sc[nt], qlr[s], kh8[2 * s], kh8[2 * s + 1]);
                }
            }

            // ---- causal mask (diagonal tiles only) ----
            const int R0 = wrow0 + (l >> 2);
            if (ks + 64 > wrow0) {
                int colb = ks + ((l & 3) << 1);
#pragma unroll
                for (int nt = 0; nt < 8; nt++) {
                    int c0 = colb + (nt << 3);
                    if (c0     > R0)     sc[nt][0] = -3.0e38f;
                    if (c0 + 1 > R0)     sc[nt][1] = -3.0e38f;
                    if (c0     > R0 + 8) sc[nt][2] = -3.0e38f;
                    if (c0 + 1 > R0 + 8) sc[nt][3] = -3.0e38f;
                }
            }

            // ---- online softmax (per-warp, registers) ----
            float tm0 = -3.0e38f, tm1 = -3.0e38f;
#pragma unroll
            for (int nt = 0; nt < 8; nt++) {
                tm0 = fmaxf(tm0, fmaxf(sc[nt][0], sc[nt][1]));
                tm1 = fmaxf(tm1, fmaxf(sc[nt][2], sc[nt][3]));
            }
            tm0 = fmaxf(tm0, __shfl_xor_sync(0xffffffffu, tm0, 1));
            tm0 = fmaxf(tm0, __shfl_xor_sync(0xffffffffu, tm0, 2));
            tm1 = fmaxf(tm1, __shfl_xor_sync(0xffffffffu, tm1, 1));
            tm1 = fmaxf(tm1, __shfl_xor_sync(0xffffffffu, tm1, 2));
            float mn0 = fmaxf(m0, tm0), mn1 = fmaxf(m1, tm1);
            float c0 = __expf(m0 - mn0), c1 = __expf(m1 - mn1);

            float ps0 = 0.f, ps1 = 0.f;
            uint32_t phi[4][4], plo[4][4];
#pragma unroll
            for (int s = 0; s < 4; s++) {
#pragma unroll
                for (int h = 0; h < 2; h++) {
                    int nt = 2 * s + h;
                    float p0 = __expf(sc[nt][0] - mn0);
                    float p1 = __expf(sc[nt][1] - mn0);
                    float p2 = __expf(sc[nt][2] - mn1);
                    float p3 = __expf(sc[nt][3] - mn1);
                    ps0 += p0 + p1;
                    ps1 += p2 + p3;
                    split2(p0, p1, phi[s][2 * h],     plo[s][2 * h]);
                    split2(p2, p3, phi[s][2 * h + 1], plo[s][2 * h + 1]);
                }
            }
            ps0 += __shfl_xor_sync(0xffffffffu, ps0, 1);
            ps0 += __shfl_xor_sync(0xffffffffu, ps0, 2);
            ps1 += __shfl_xor_sync(0xffffffffu, ps1, 1);
            ps1 += __shfl_xor_sync(0xffffffffu, ps1, 2);
            ls0 = ls0 * c0 + ps0;
            ls1 = ls1 * c1 + ps1;
            m0 = mn0; m1 = mn1;

            // ---- rescale O, then O += P V ----
#pragma unroll
            for (int nt = 0; nt < 8; nt++) {
                o[nt][0] *= c0; o[nt][1] *= c0;
                o[nt][2] *= c1; o[nt][3] *= c1;
            }
#pragma unroll
            for (int nt = 0; nt < 8; nt++) {
                int row = (nt << 3) + brow;
                uint32_t rb = sb + (uint32_t)row * 128u;
                uint32_t s0 = (uint32_t)((bu       ^ (row & 7)) << 4);
                uint32_t s1 = (uint32_t)(((4 + bu) ^ (row & 7)) << 4);
                uint32_t vh8[8], vl8[8];
                ldsm4(vh8,     rb + VHI_O + s0);
                ldsm4(vh8 + 4, rb + VHI_O + s1);
                ldsm4(vl8,     rb + VLO_O + s0);
                ldsm4(vl8 + 4, rb + VLO_O + s1);
#pragma unroll
                for (int s = 0; s < 4; s++) {
                    mma16816(o[nt], phi[s], vh8[2 * s], vh8[2 * s + 1]);
                    mma16816(o[nt], phi[s], vl8[2 * s], vl8[2 * s + 1]);
                    mma16816(o[nt], plo[s], vh8[2 * s], vh8[2 * s + 1]);
                }
            }
        }
        __syncthreads();
    }

    // ---- write output ----
    const float inv0 = 1.f / ls0, inv1 = 1.f / ls1;
    const int R0g = q0 + (w << 4) + (l >> 2);
    float* o0p = out + (((size_t)(b * Tn + R0g)) << 6) + ((l & 3) << 1);
    float* o1p = o0p + (8 << 6);
#pragma unroll
    for (int nt = 0; nt < 8; nt++) {
        *(float2*)(o0p + (nt << 3)) = make_float2(o[nt][0] * inv0, o[nt][1] * inv0);
        *(float2*)(o1p + (nt << 3)) = make_float2(o[nt][2] * inv1, o[nt][3] * inv1);
    }
}

// ===================== launch =====================
extern "C" void kernel_launch(void* const* d_in, const int* in_sizes, int n_in,
                              void* d_out, int out_size)
{
    const float* x  = (const float*)d_in[0];
    const float* WQ = (const float*)d_in[1];
    const float* WK = (const float*)d_in[2];
    const float* WV = (const float*)d_in[3];
    float* out = (float*)d_out;

    cudaFuncSetAttribute(attn_kernel,
                         cudaFuncAttributeMaxDynamicSharedMemorySize, SMEM_BYTES);

    proj_kernel<<<(Bn * Tn) / 128, 256>>>(x, WQ, WK, WV);
    attn_kernel<<<256, 256, SMEM_BYTES>>>(out);
}

// round 4
// speedup vs baseline: 4.4994x; 1.4346x over previous
#include <cuda_runtime.h>
#include <cuda_bf16.h>
#include <cstdint>

#define Bn  16
#define Tn  2048
#define Cn  384
#define DKn 64

// Pre-split bf16 operands produced by proj kernel
__device__ __align__(16) __nv_bfloat16 g_qhi [Bn * Tn * DKn];
__device__ __align__(16) __nv_bfloat16 g_qlo [Bn * Tn * DKn];
__device__ __align__(16) __nv_bfloat16 g_khi [Bn * Tn * DKn];
__device__ __align__(16) __nv_bfloat16 g_klo [Bn * Tn * DKn];
__device__ __align__(16) __nv_bfloat16 g_vthi[Bn * DKn * Tn];   // [b][d][t]
__device__ __align__(16) __nv_bfloat16 g_vtlo[Bn * DKn * Tn];

// ===================== helpers =====================
__device__ __forceinline__ uint32_t smem_u32(const void* p) {
    uint32_t a;
    asm("{ .reg .u64 t; cvta.to.shared.u64 t, %1; cvt.u32.u64 %0, t; }" : "=r"(a) : "l"(p));
    return a;
}
__device__ __forceinline__ uint32_t pack2(float e0, float e1) {
    uint32_t r;
    asm("cvt.rn.bf16x2.f32 %0, %1, %2;" : "=r"(r) : "f"(e1), "f"(e0));
    return r;
}
__device__ __forceinline__ void split2(float e0, float e1, uint32_t& hi, uint32_t& lo) {
    hi = pack2(e0, e1);
    float h0 = __uint_as_float(hi << 16);
    float h1 = __uint_as_float(hi & 0xffff0000u);
    lo = pack2(e0 - h0, e1 - h1);
}
__device__ __forceinline__ void ldsm4(uint32_t r[4], uint32_t addr) {
    asm volatile("ldmatrix.sync.aligned.m8n8.x4.shared.b16 {%0,%1,%2,%3}, [%4];"
        : "=r"(r[0]), "=r"(r[1]), "=r"(r[2]), "=r"(r[3]) : "r"(addr));
}
__device__ __forceinline__ void mma16816(float c[4], const uint32_t a[4],
                                         uint32_t b0, uint32_t b1) {
    asm volatile(
        "mma.sync.aligned.m16n8k16.row.col.f32.bf16.bf16.f32 "
        "{%0,%1,%2,%3},{%4,%5,%6,%7},{%8,%9},{%0,%1,%2,%3};"
        : "+f"(c[0]), "+f"(c[1]), "+f"(c[2]), "+f"(c[3])
        : "r"(a[0]), "r"(a[1]), "r"(a[2]), "r"(a[3]), "r"(b0), "r"(b1));
}
#define STS128(a, v) \
    asm volatile("st.shared.v4.b32 [%0], {%1,%2,%3,%4};" \
        :: "r"(a), "r"((v).x), "r"((v).y), "r"((v).z), "r"((v).w) : "memory")
#define STS64(a, r0, r1) \
    asm volatile("st.shared.v2.b32 [%0], {%1,%2};" :: "r"(a), "r"(r0), "r"(r1) : "memory")
#define STS32(a, r0) \
    asm volatile("st.shared.b32 [%0], %1;" :: "r"(a), "r"(r0) : "memory")

extern __shared__ __align__(16) char dsmem[];

// ===================== projection (tensor-core, bf16 3-term split) ==========
// out[r][n] = sum_k x[r][k] * W[k][n],  N=192 = [WQ|WK|WV].
// CTA: 128 rows x 192 cols; warp w: rows w*16..w*16+15, all 192 cols.
#define XS_HI_O 0u
#define XS_LO_O 16384u
#define WT_HI_O 32768u            // 192 rows x 128B  (bf16 [n][k], swizzled)
#define WT_LO_O 57344u
#define WPAD_O  81920u            // fp32 staging 3 x [64][65]  (also V overlay)
#define PROJ_SMEM (131840u + 128u)

__global__ __launch_bounds__(256, 1) void proj_tc_kernel(
    const float* __restrict__ x,
    const float* __restrict__ WQ,
    const float* __restrict__ WK,
    const float* __restrict__ WV)
{
    uint32_t raw = smem_u32(dsmem);
    uint32_t sb  = (raw + 127u) & ~127u;
    char*    bp  = dsmem + (sb - raw);
    float*   wpad = (float*)(bp + WPAD_O);
    float (*vt)[65] = (float(*)[65])(bp + WPAD_O);

    const int tid = threadIdx.x;
    const int w   = tid >> 5;
    const int l   = tid & 31;
    const int r0  = blockIdx.x * 128;

    float acc[24][4];
#pragma unroll
    for (int i = 0; i < 24; i++)
#pragma unroll
        for (int j = 0; j < 4; j++) acc[i][j] = 0.f;

    const int arow = (w << 4) + (l & 7) + (((l >> 3) & 1) << 3);

    for (int kk = 0; kk < Cn; kk += 64) {
        // ---- phase 1a: x chunk -> split bf16 hi/lo, swizzled ----
#pragma unroll
        for (int it = 0; it < 8; it++) {
            int idx = tid + (it << 8);
            int r = idx >> 4, k4 = (idx & 15) << 2;
            float4 v = *(const float4*)(x + (size_t)(r0 + r) * Cn + kk + k4);
            uint32_t h0, l0, h1, l1;
            split2(v.x, v.y, h0, l0);
            split2(v.z, v.w, h1, l1);
            uint32_t sw = (uint32_t)r * 128u
                        + (uint32_t)((((k4 >> 3) ^ (r & 7)) << 4))
                        + (uint32_t)((k4 & 7) << 1);
            STS64(sb + XS_HI_O + sw, h0, h1);
            STS64(sb + XS_LO_O + sw, l0, l1);
        }
        // ---- phase 1b: W chunk fp32 -> padded smem (coalesced) ----
#pragma unroll
        for (int it = 0; it < 12; it++) {
            int idx = tid + (it << 8);              // < 3072
            int m = idx >> 10, rem = idx & 1023;
            int k = rem >> 4, nf = (rem & 15) << 2;
            const float* W = (m == 0) ? WQ : ((m == 1) ? WK : WV);
            float4 v = *(const float4*)(W + (size_t)(kk + k) * DKn + nf);
            float* wp = wpad + m * 4160 + k * 65 + nf;
            wp[0] = v.x; wp[1] = v.y; wp[2] = v.z; wp[3] = v.w;
        }
        __syncthreads();

        // ---- phase 2: transpose W -> wt[n][k] bf16 hi/lo, swizzled ----
#pragma unroll
        for (int it = 0; it < 24; it++) {
            int idx = tid + (it << 8);              // < 6144
            int k2 = idx & 31, n = idx >> 5;        // k2 = pair of k
            int m = n >> 6, nl = n & 63;
            const float* wp = wpad + m * 4160 + (k2 << 1) * 65 + nl;
            float e0 = wp[0], e1 = wp[65];
            uint32_t h, lo;
            split2(e0, e1, h, lo);
            uint32_t sw = (uint32_t)n * 128u
                        + (uint32_t)((((k2 >> 2) ^ (n & 7)) << 4))
                        + (uint32_t)((k2 & 3) << 2);
            STS32(sb + WT_HI_O + sw, h);
            STS32(sb + WT_LO_O + sw, lo);
        }
        __syncthreads();

        // ---- mma: A = x rows (m16), B = wt rows (n8) ----
        uint32_t ah[4][4], al[4][4];
        {
            uint32_t rb = sb + (uint32_t)arow * 128u;
#pragma unroll
            for (int ks = 0; ks < 4; ks++) {
                int u = (ks << 1) + (l >> 4);
                uint32_t sw = (uint32_t)((u ^ (arow & 7)) << 4);
                ldsm4(ah[ks], rb + XS_HI_O + sw);
                ldsm4(al[ks], rb + XS_LO_O + sw);
            }
        }
        const int brow = l & 7;
        const int bu   = l >> 3;
#pragma unroll
        for (int nt = 0; nt < 24; nt++) {
            int rowb = (nt << 3) + brow;
            uint32_t rb = sb + (uint32_t)rowb * 128u;
            uint32_t s0 = (uint32_t)((bu       ^ (rowb & 7)) << 4);
            uint32_t s1 = (uint32_t)(((4 + bu) ^ (rowb & 7)) << 4);
            uint32_t bh[8], bl[8];
            ldsm4(bh,     rb + WT_HI_O + s0);
            ldsm4(bh + 4, rb + WT_HI_O + s1);
            ldsm4(bl,     rb + WT_LO_O + s0);
            ldsm4(bl + 4, rb + WT_LO_O + s1);
#pragma unroll
            for (int s = 0; s < 4; s++) {
                mma16816(acc[nt], ah[s], bh[2 * s], bh[2 * s + 1]);
                mma16816(acc[nt], ah[s], bl[2 * s], bl[2 * s + 1]);
                mma16816(acc[nt], al[s], bh[2 * s], bh[2 * s + 1]);
            }
        }
        __syncthreads();
    }

    // ---- epilogue: Q (x0.125) / K split-store; V staged for transpose ----
    const int rl = (w << 4) + (l >> 2);
    const int cc = (l & 3) << 1;
    const size_t row0 = (size_t)(r0 + rl);
#pragma unroll
    for (int nt = 0; nt < 8; nt++) {
        int c = (nt << 3) + cc;
        uint32_t h, lo;
        split2(acc[nt][0] * 0.125f, acc[nt][1] * 0.125f, h, lo);
        *(uint32_t*)(g_qhi + row0 * 64 + c) = h;
        *(uint32_t*)(g_qlo + row0 * 64 + c) = lo;
        split2(acc[nt][2] * 0.125f, acc[nt][3] * 0.125f, h, lo);
        *(uint32_t*)(g_qhi + (row0 + 8) * 64 + c) = h;
        *(uint32_t*)(g_qlo + (row0 + 8) * 64 + c) = lo;

        split2(acc[nt + 8][0], acc[nt + 8][1], h, lo);
        *(uint32_t*)(g_khi + row0 * 64 + c) = h;
        *(uint32_t*)(g_klo + row0 * 64 + c) = lo;
        split2(acc[nt + 8][2], acc[nt + 8][3], h, lo);
        *(uint32_t*)(g_khi + (row0 + 8) * 64 + c) = h;
        *(uint32_t*)(g_klo + (row0 + 8) * 64 + c) = lo;

        vt[rl][c]         = acc[nt + 16][0];
        vt[rl][c + 1]     = acc[nt + 16][1];
        vt[rl + 8][c]     = acc[nt + 16][2];
        vt[rl + 8][c + 1] = acc[nt + 16][3];
    }
    __syncthreads();

    // ---- transposed V write: g_vt[b][d][t], split bf16 ----
    {
        const int b  = r0 >> 11;
        const int t0 = r0 & 2047;
        const int d  = tid >> 2;
        const int tq = (tid & 3) << 5;
#pragma unroll
        for (int g = 0; g < 8; g++) {
            int tl = tq + g * 4;
            float v0 = vt[tl][d], v1 = vt[tl + 1][d];
            float v2 = vt[tl + 2][d], v3 = vt[tl + 3][d];
            uint32_t h0, h1, l0, l1;
            split2(v0, v1, h0, l0);
            split2(v2, v3, h1, l1);
            size_t off = ((size_t)(b * DKn + d) << 11) + t0 + tl;
            *(uint2*)(g_vthi + off) = make_uint2(h0, h1);
            *(uint2*)(g_vtlo + off) = make_uint2(l0, l1);
        }
    }
}

// ===================== attention (unchanged from round 3) =====================
#define QHI_O 0u
#define QLO_O 16384u
#define KHI_O 32768u
#define KLO_O 40960u
#define VHI_O 49152u
#define VLO_O 57344u
#define SMEM_BYTES (65536u + 1024u)

__global__ __launch_bounds__(256, 1) void attn_kernel(float* __restrict__ out)
{
    uint32_t raw = smem_u32(dsmem);
    uint32_t sb  = (raw + 127u) & ~127u;

    const int tid = threadIdx.x;
    const int w   = tid >> 5;
    const int l   = tid & 31;

    const int bx = blockIdx.x;
    const int qt = 15 - (bx >> 4);          // heavy q-tiles first
    const int b  = bx & 15;
    const int q0 = qt << 7;

    // ---- stage Q tiles (bf16 hi/lo), swizzled ----
    {
        const uint4* qh = (const uint4*)(g_qhi + (((size_t)(b * Tn + q0)) << 6));
        const uint4* ql = (const uint4*)(g_qlo + (((size_t)(b * Tn + q0)) << 6));
#pragma unroll
        for (int i = 0; i < 4; i++) {
            int idx = tid + (i << 8);
            int r = idx >> 3, u = idx & 7;
            uint32_t sw = (uint32_t)r * 128u + (uint32_t)((u ^ (r & 7)) << 4);
            uint4 vh = qh[idx], vl = ql[idx];
            STS128(sb + QHI_O + sw, vh);
            STS128(sb + QLO_O + sw, vl);
        }
    }
    __syncthreads();

    uint32_t qh[4][4], qlr[4][4];
    {
        int arow = (w << 4) + (l & 7) + (((l >> 3) & 1) << 3);
        uint32_t rb = sb + (uint32_t)arow * 128u;
#pragma unroll
        for (int kk = 0; kk < 4; kk++) {
            int u = (kk << 1) + (l >> 4);
            uint32_t sw = (uint32_t)((u ^ (arow & 7)) << 4);
            ldsm4(qh[kk],  rb + QHI_O + sw);
            ldsm4(qlr[kk], rb + QLO_O + sw);
        }
    }

    float m0 = -3.0e38f, m1 = -3.0e38f, ls0 = 0.f, ls1 = 0.f;
    float o[8][4];
#pragma unroll
    for (int i = 0; i < 8; i++)
#pragma unroll
        for (int j = 0; j < 4; j++) o[i][j] = 0.f;

    const int kend  = q0 + 128;
    const int wrow0 = q0 + (w << 4);

    for (int ks = 0; ks < kend; ks += 64) {
        {
            const uint4* kh = (const uint4*)(g_khi + (((size_t)(b * Tn + ks)) << 6));
            const uint4* kl = (const uint4*)(g_klo + (((size_t)(b * Tn + ks)) << 6));
            const __nv_bfloat16* vhb = g_vthi + (((size_t)(b * DKn)) << 11) + ks;
            const __nv_bfloat16* vlb = g_vtlo + (((size_t)(b * DKn)) << 11) + ks;
#pragma unroll
            for (int i = 0; i < 2; i++) {
                int idx = tid + (i << 8);
                int r = idx >> 3, u = idx & 7;
                uint32_t sw = (uint32_t)r * 128u + (uint32_t)((u ^ (r & 7)) << 4);
                uint4 a = kh[idx], c = kl[idx];
                STS128(sb + KHI_O + sw, a);
                STS128(sb + KLO_O + sw, c);
                uint4 e = *(const uint4*)(vhb + ((size_t)r << 11) + (u << 3));
                uint4 f = *(const uint4*)(vlb + ((size_t)r << 11) + (u << 3));
                STS128(sb + VHI_O + sw, e);
                STS128(sb + VLO_O + sw, f);
            }
        }
        __syncthreads();

        if (ks <= wrow0 + 15) {
            const int brow = l & 7;
            const int bu   = l >> 3;

            float sc[8][4];
#pragma unroll
            for (int nt = 0; nt < 8; nt++) {
                int row = (nt << 3) + brow;
                uint32_t rb = sb + (uint32_t)row * 128u;
                uint32_t s0 = (uint32_t)((bu       ^ (row & 7)) << 4);
                uint32_t s1 = (uint32_t)(((4 + bu) ^ (row & 7)) << 4);
                uint32_t kh8[8], kl8[8];
                ldsm4(kh8,     rb + KHI_O + s0);
                ldsm4(kh8 + 4, rb + KHI_O + s1);
                ldsm4(kl8,     rb + KLO_O + s0);
                ldsm4(kl8 + 4, rb + KLO_O + s1);
#pragma unroll
                for (int j = 0; j < 4; j++) sc[nt][j] = 0.f;
#pragma unroll
                for (int s = 0; s < 4; s++) {
                    mma16816(sc[nt], qh[s],  kh8[2 * s], kh8[2 * s + 1]);
                    mma16816(sc[nt], qh[s],  kl8[2 * s], kl8[2 * s + 1]);
                    mma16816(sc[nt], qlr[s], kh8[2 * s], kh8[2 * s + 1]);
                }
            }

            const int R0 = wrow0 + (l >> 2);
            if (ks + 64 > wrow0) {
                int colb = ks + ((l & 3) << 1);
#pragma unroll
                for (int nt = 0; nt < 8; nt++) {
                    int c0 = colb + (nt << 3);
                    if (c0     > R0)     sc[nt][0] = -3.0e38f;
                    if (c0 + 1 > R0)     sc[nt][1] = -3.0e38f;
                    if (c0     > R0 + 8) sc[nt][2] = -3.0e38f;
                    if (c0 + 1 > R0 + 8) sc[nt][3] = -3.0e38f;
                }
            }

            float tm0 = -3.0e38f, tm1 = -3.0e38f;
#pragma unroll
            for (int nt = 0; nt < 8; nt++) {
                tm0 = fmaxf(tm0, fmaxf(sc[nt][0], sc[nt][1]));
                tm1 = fmaxf(tm1, fmaxf(sc[nt][2], sc[nt][3]));
            }
            tm0 = fmaxf(tm0, __shfl_xor_sync(0xffffffffu, tm0, 1));
            tm0 = fmaxf(tm0, __shfl_xor_sync(0xffffffffu, tm0, 2));
            tm1 = fmaxf(tm1, __shfl_xor_sync(0xffffffffu, tm1, 1));
            tm1 = fmaxf(tm1, __shfl_xor_sync(0xffffffffu, tm1, 2));
            float mn0 = fmaxf(m0, tm0), mn1 = fmaxf(m1, tm1);
            float c0 = __expf(m0 - mn0), c1 = __expf(m1 - mn1);

            float ps0 = 0.f, ps1 = 0.f;
            uint32_t phi[4][4], plo[4][4];
#pragma unroll
            for (int s = 0; s < 4; s++) {
#pragma unroll
                for (int h = 0; h < 2; h++) {
                    int nt = 2 * s + h;
                    float p0 = __expf(sc[nt][0] - mn0);
                    float p1 = __expf(sc[nt][1] - mn0);
                    float p2 = __expf(sc[nt][2] - mn1);
                    float p3 = __expf(sc[nt][3] - mn1);
                    ps0 += p0 + p1;
                    ps1 += p2 + p3;
                    split2(p0, p1, phi[s][2 * h],     plo[s][2 * h]);
                    split2(p2, p3, phi[s][2 * h + 1], plo[s][2 * h + 1]);
                }
            }
            ps0 += __shfl_xor_sync(0xffffffffu, ps0, 1);
            ps0 += __shfl_xor_sync(0xffffffffu, ps0, 2);
            ps1 += __shfl_xor_sync(0xffffffffu, ps1, 1);
            ps1 += __shfl_xor_sync(0xffffffffu, ps1, 2);
            ls0 = ls0 * c0 + ps0;
            ls1 = ls1 * c1 + ps1;
            m0 = mn0; m1 = mn1;

#pragma unroll
            for (int nt = 0; nt < 8; nt++) {
                o[nt][0] *= c0; o[nt][1] *= c0;
                o[nt][2] *= c1; o[nt][3] *= c1;
            }
#pragma unroll
            for (int nt = 0; nt < 8; nt++) {
                int row = (nt << 3) + brow;
                uint32_t rb = sb + (uint32_t)row * 128u;
                uint32_t s0 = (uint32_t)((bu       ^ (row & 7)) << 4);
                uint32_t s1 = (uint32_t)(((4 + bu) ^ (row & 7)) << 4);
                uint32_t vh8[8], vl8[8];
                ldsm4(vh8,     rb + VHI_O + s0);
                ldsm4(vh8 + 4, rb + VHI_O + s1);
                ldsm4(vl8,     rb + VLO_O + s0);
                ldsm4(vl8 + 4, rb + VLO_O + s1);
#pragma unroll
                for (int s = 0; s < 4; s++) {
                    mma16816(o[nt], phi[s], vh8[2 * s], vh8[2 * s + 1]);
                    mma16816(o[nt], phi[s], vl8[2 * s], vl8[2 * s + 1]);
                    mma16816(o[nt], plo[s], vh8[2 * s], vh8[2 * s + 1]);
                }
            }
        }
        __syncthreads();
    }

    const float inv0 = 1.f / ls0, inv1 = 1.f / ls1;
    const int R0g = q0 + (w << 4) + (l >> 2);
    float* o0p = out + (((size_t)(b * Tn + R0g)) << 6) + ((l & 3) << 1);
    float* o1p = o0p + (8 << 6);
#pragma unroll
    for (int nt = 0; nt < 8; nt++) {
        *(float2*)(o0p + (nt << 3)) = make_float2(o[nt][0] * inv0, o[nt][1] * inv0);
        *(float2*)(o1p + (nt << 3)) = make_float2(o[nt][2] * inv1, o[nt][3] * inv1);
    }
}

// ===================== launch =====================
extern "C" void kernel_launch(void* const* d_in, const int* in_sizes, int n_in,
                              void* d_out, int out_size)
{
    const float* x  = (const float*)d_in[0];
    const float* WQ = (const float*)d_in[1];
    const float* WK = (const float*)d_in[2];
    const float* WV = (const float*)d_in[3];
    float* out = (float*)d_out;

    cudaFuncSetAttribute(proj_tc_kernel,
                         cudaFuncAttributeMaxDynamicSharedMemorySize, PROJ_SMEM);
    cudaFuncSetAttribute(attn_kernel,
                         cudaFuncAttributeMaxDynamicSharedMemorySize, SMEM_BYTES);

    proj_tc_kernel<<<(Bn * Tn) / 128, 256, PROJ_SMEM>>>(x, WQ, WK, WV);
    attn_kernel<<<256, 256, SMEM_BYTES>>>(out);
}

// round 5
// speedup vs baseline: 5.2917x; 1.1761x over previous
#include <cuda_runtime.h>
#include <cuda_bf16.h>
#include <cstdint>

#define Bn  16
#define Tn  2048
#define Cn  384
#define DKn 64

// Pre-split bf16 operands
__device__ __align__(16) __nv_bfloat16 g_qhi [Bn * Tn * DKn];
__device__ __align__(16) __nv_bfloat16 g_qlo [Bn * Tn * DKn];
__device__ __align__(16) __nv_bfloat16 g_khi [Bn * Tn * DKn];
__device__ __align__(16) __nv_bfloat16 g_klo [Bn * Tn * DKn];
__device__ __align__(16) __nv_bfloat16 g_vthi[Bn * DKn * Tn];   // [b][d][t]
__device__ __align__(16) __nv_bfloat16 g_vtlo[Bn * DKn * Tn];
// Pre-transposed, pre-split weights: [n][k] with n in 0..191 = [Q|K|V]
__device__ __align__(16) __nv_bfloat16 g_wthi[192 * Cn];
__device__ __align__(16) __nv_bfloat16 g_wtlo[192 * Cn];

// ===================== helpers =====================
__device__ __forceinline__ uint32_t smem_u32(const void* p) {
    uint32_t a;
    asm("{ .reg .u64 t; cvta.to.shared.u64 t, %1; cvt.u32.u64 %0, t; }" : "=r"(a) : "l"(p));
    return a;
}
__device__ __forceinline__ uint32_t pack2(float e0, float e1) {
    uint32_t r;
    asm("cvt.rn.bf16x2.f32 %0, %1, %2;" : "=r"(r) : "f"(e1), "f"(e0));
    return r;
}
__device__ __forceinline__ void split2(float e0, float e1, uint32_t& hi, uint32_t& lo) {
    hi = pack2(e0, e1);
    float h0 = __uint_as_float(hi << 16);
    float h1 = __uint_as_float(hi & 0xffff0000u);
    lo = pack2(e0 - h0, e1 - h1);
}
__device__ __forceinline__ void ldsm4(uint32_t r[4], uint32_t addr) {
    asm volatile("ldmatrix.sync.aligned.m8n8.x4.shared.b16 {%0,%1,%2,%3}, [%4];"
        : "=r"(r[0]), "=r"(r[1]), "=r"(r[2]), "=r"(r[3]) : "r"(addr));
}
__device__ __forceinline__ void mma16816(float c[4], const uint32_t a[4],
                                         uint32_t b0, uint32_t b1) {
    asm volatile(
        "mma.sync.aligned.m16n8k16.row.col.f32.bf16.bf16.f32 "
        "{%0,%1,%2,%3},{%4,%5,%6,%7},{%8,%9},{%0,%1,%2,%3};"
        : "+f"(c[0]), "+f"(c[1]), "+f"(c[2]), "+f"(c[3])
        : "r"(a[0]), "r"(a[1]), "r"(a[2]), "r"(a[3]), "r"(b0), "r"(b1));
}
#define STS128(a, v) \
    asm volatile("st.shared.v4.b32 [%0], {%1,%2,%3,%4};" \
        :: "r"(a), "r"((v).x), "r"((v).y), "r"((v).z), "r"((v).w) : "memory")
#define STS64(a, r0, r1) \
    asm volatile("st.shared.v2.b32 [%0], {%1,%2};" :: "r"(a), "r"(r0), "r"(r1) : "memory")
#define CP16(sm, gp) \
    asm volatile("cp.async.cg.shared.global [%0], [%1], 16;" :: "r"(sm), "l"(gp) : "memory")
#define CP_COMMIT() asm volatile("cp.async.commit_group;" ::: "memory")
#define CP_WAIT(n)  asm volatile("cp.async.wait_group %0;" :: "n"(n) : "memory")

extern __shared__ __align__(16) char dsmem[];

// ===================== prep_w: transpose + split W once =====================
__global__ __launch_bounds__(128) void prep_w(
    const float* __restrict__ WQ,
    const float* __restrict__ WK,
    const float* __restrict__ WV)
{
    const int n  = blockIdx.x;            // 0..191 = output column
    const int m  = n >> 6, nl = n & 63;
    const float* W = (m == 0) ? WQ : ((m == 1) ? WK : WV);
    for (int k = threadIdx.x; k < Cn; k += 128) {
        float v = W[(size_t)k * DKn + nl];
        __nv_bfloat16 h = __float2bfloat16(v);
        float r = v - __bfloat162float(h);
        g_wthi[n * Cn + k] = h;
        g_wtlo[n * Cn + k] = __float2bfloat16(r);
    }
}

// ===================== projection (bf16 3-term split, cp.async W) ==========
// smem: XS hi/lo 2x16KB @0; WT double buffer 2x48KB @32768 (hi +0, lo +24576)
#define P_XHI 0u
#define P_XLO 16384u
#define P_WT0 32768u
#define P_WSTRIDE 49152u
#define PROJ_SMEM (131072u + 128u)

__device__ __forceinline__ void stage_wt_async(uint32_t dst, int kk, int tid) {
#pragma unroll
    for (int i = 0; i < 6; i++) {            // 1536 = 192 rows x 8 units
        int idx = tid + (i << 8);
        int n = idx >> 3, u = idx & 7;
        uint32_t sw = (uint32_t)n * 128u + (uint32_t)((u ^ (n & 7)) << 4);
        CP16(dst + sw,          g_wthi + n * Cn + kk + (u << 3));
        CP16(dst + 24576u + sw, g_wtlo + n * Cn + kk + (u << 3));
    }
}

__global__ __launch_bounds__(256, 1) void proj_tc_kernel(const float* __restrict__ x)
{
    uint32_t raw = smem_u32(dsmem);
    uint32_t sb  = (raw + 127u) & ~127u;
    char*    bp  = dsmem + (sb - raw);
    float (*vt)[65] = (float(*)[65])(bp + P_WT0);   // epilogue overlay

    const int tid = threadIdx.x;
    const int w   = tid >> 5;
    const int l   = tid & 31;
    const int r0  = blockIdx.x * 128;

    float acc[24][4];
#pragma unroll
    for (int i = 0; i < 24; i++)
#pragma unroll
        for (int j = 0; j < 4; j++) acc[i][j] = 0.f;

    const int arow = (w << 4) + (l & 7) + (((l >> 3) & 1) << 3);
    const int brow = l & 7;
    const int bu   = l >> 3;

    stage_wt_async(sb + P_WT0, 0, tid);
    CP_COMMIT();

    for (int c = 0; c < Cn / 64; c++) {
        const int kk = c * 64;
        // ---- stage x chunk: LDG -> split -> STS (swizzled) ----
#pragma unroll
        for (int it = 0; it < 8; it++) {
            int idx = tid + (it << 8);
            int r = idx >> 4, k4 = (idx & 15) << 2;
            float4 v = *(const float4*)(x + (size_t)(r0 + r) * Cn + kk + k4);
            uint32_t h0, l0, h1, l1;
            split2(v.x, v.y, h0, l0);
            split2(v.z, v.w, h1, l1);
            uint32_t sw = (uint32_t)r * 128u
                        + (uint32_t)((((k4 >> 3) ^ (r & 7)) << 4))
                        + (uint32_t)((k4 & 7) << 1);
            STS64(sb + P_XHI + sw, h0, h1);
            STS64(sb + P_XLO + sw, l0, l1);
        }
        if (c + 1 < Cn / 64) {
            stage_wt_async(sb + P_WT0 + (uint32_t)((c + 1) & 1) * P_WSTRIDE,
                           kk + 64, tid);
            CP_COMMIT();
            CP_WAIT(1);
        } else {
            CP_WAIT(0);
        }
        __syncthreads();

        const uint32_t wtb = sb + P_WT0 + (uint32_t)(c & 1) * P_WSTRIDE;

        uint32_t ah[4][4], al[4][4];
        {
            uint32_t rb = sb + (uint32_t)arow * 128u;
#pragma unroll
            for (int ks = 0; ks < 4; ks++) {
                int u = (ks << 1) + (l >> 4);
                uint32_t sw = (uint32_t)((u ^ (arow & 7)) << 4);
                ldsm4(ah[ks], rb + P_XHI + sw);
                ldsm4(al[ks], rb + P_XLO + sw);
            }
        }
#pragma unroll
        for (int nt = 0; nt < 24; nt++) {
            int rowb = (nt << 3) + brow;
            uint32_t rb = wtb + (uint32_t)rowb * 128u;
            uint32_t s0 = (uint32_t)((bu       ^ (rowb & 7)) << 4);
            uint32_t s1 = (uint32_t)(((4 + bu) ^ (rowb & 7)) << 4);
            uint32_t bh[8], bl[8];
            ldsm4(bh,     rb + s0);
            ldsm4(bh + 4, rb + s1);
            ldsm4(bl,     rb + 24576u + s0);
            ldsm4(bl + 4, rb + 24576u + s1);
#pragma unroll
            for (int s = 0; s < 4; s++) {
                mma16816(acc[nt], ah[s], bh[2 * s], bh[2 * s + 1]);
                mma16816(acc[nt], ah[s], bl[2 * s], bl[2 * s + 1]);
                mma16816(acc[nt], al[s], bh[2 * s], bh[2 * s + 1]);
            }
        }
        __syncthreads();
    }

    // ---- epilogue: Q (x0.125) / K split-store; V staged for transpose ----
    const int rl = (w << 4) + (l >> 2);
    const int cc = (l & 3) << 1;
    const size_t row0 = (size_t)(r0 + rl);
#pragma unroll
    for (int nt = 0; nt < 8; nt++) {
        int cidx = (nt << 3) + cc;
        uint32_t h, lo;
        split2(acc[nt][0] * 0.125f, acc[nt][1] * 0.125f, h, lo);
        *(uint32_t*)(g_qhi + row0 * 64 + cidx) = h;
        *(uint32_t*)(g_qlo + row0 * 64 + cidx) = lo;
        split2(acc[nt][2] * 0.125f, acc[nt][3] * 0.125f, h, lo);
        *(uint32_t*)(g_qhi + (row0 + 8) * 64 + cidx) = h;
        *(uint32_t*)(g_qlo + (row0 + 8) * 64 + cidx) = lo;

        split2(acc[nt + 8][0], acc[nt + 8][1], h, lo);
        *(uint32_t*)(g_khi + row0 * 64 + cidx) = h;
        *(uint32_t*)(g_klo + row0 * 64 + cidx) = lo;
        split2(acc[nt + 8][2], acc[nt + 8][3], h, lo);
        *(uint32_t*)(g_khi + (row0 + 8) * 64 + cidx) = h;
        *(uint32_t*)(g_klo + (row0 + 8) * 64 + cidx) = lo;

        vt[rl][cidx]         = acc[nt + 16][0];
        vt[rl][cidx + 1]     = acc[nt + 16][1];
        vt[rl + 8][cidx]     = acc[nt + 16][2];
        vt[rl + 8][cidx + 1] = acc[nt + 16][3];
    }
    __syncthreads();

    {
        const int b  = r0 >> 11;
        const int t0 = r0 & 2047;
        const int d  = tid >> 2;
        const int tq = (tid & 3) << 5;
#pragma unroll
        for (int g = 0; g < 8; g++) {
            int tl = tq + g * 4;
            float v0 = vt[tl][d], v1 = vt[tl + 1][d];
            float v2 = vt[tl + 2][d], v3 = vt[tl + 3][d];
            uint32_t h0, h1, l0, l1;
            split2(v0, v1, h0, l0);
            split2(v2, v3, h1, l1);
            size_t off = ((size_t)(b * DKn + d) << 11) + t0 + tl;
            *(uint2*)(g_vthi + off) = make_uint2(h0, h1);
            *(uint2*)(g_vtlo + off) = make_uint2(l0, l1);
        }
    }
}

// ===================== attention (cp.async double-buffered K/V) ==============
// smem: Q hi/lo 2x16KB @0; KV double buffer @32768, each 32KB:
//   KHI +0, KLO +8192, VHI +16384, VLO +24576; buffer stride 32768.
#define A_QHI 0u
#define A_QLO 16384u
#define A_KV0 32768u
#define A_KHI 0u
#define A_KLO 8192u
#define A_VHI 16384u
#define A_VLO 24576u
#define ATTN_SMEM (98304u + 128u)

__device__ __forceinline__ void stage_kv_async(uint32_t dst, int b, int ks, int tid) {
    const __nv_bfloat16* kh = g_khi + (((size_t)(b * Tn + ks)) << 6);
    const __nv_bfloat16* kl = g_klo + (((size_t)(b * Tn + ks)) << 6);
    const __nv_bfloat16* vh = g_vthi + (((size_t)(b * DKn)) << 11) + ks;
    const __nv_bfloat16* vl = g_vtlo + (((size_t)(b * DKn)) << 11) + ks;
#pragma unroll
    for (int i = 0; i < 2; i++) {
        int idx = tid + (i << 8);
        int r = idx >> 3, u = idx & 7;
        uint32_t sw = (uint32_t)r * 128u + (uint32_t)((u ^ (r & 7)) << 4);
        CP16(dst + A_KHI + sw, kh + (r << 6) + (u << 3));
        CP16(dst + A_KLO + sw, kl + (r << 6) + (u << 3));
        CP16(dst + A_VHI + sw, vh + ((size_t)r << 11) + (u << 3));
        CP16(dst + A_VLO + sw, vl + ((size_t)r << 11) + (u << 3));
    }
}

__global__ __launch_bounds__(256, 1) void attn_kernel(float* __restrict__ out)
{
    uint32_t raw = smem_u32(dsmem);
    uint32_t sb  = (raw + 127u) & ~127u;

    const int tid = threadIdx.x;
    const int w   = tid >> 5;
    const int l   = tid & 31;

    const int bx = blockIdx.x;
    const int qt = 15 - (bx >> 4);          // heavy q-tiles first
    const int b  = bx & 15;
    const int q0 = qt << 7;

    // prefetch first K/V tile while staging Q
    stage_kv_async(sb + A_KV0, b, 0, tid);
    CP_COMMIT();

    {
        const uint4* qh = (const uint4*)(g_qhi + (((size_t)(b * Tn + q0)) << 6));
        const uint4* ql = (const uint4*)(g_qlo + (((size_t)(b * Tn + q0)) << 6));
#pragma unroll
        for (int i = 0; i < 4; i++) {
            int idx = tid + (i << 8);
            int r = idx >> 3, u = idx & 7;
            uint32_t sw = (uint32_t)r * 128u + (uint32_t)((u ^ (r & 7)) << 4);
            uint4 vh = qh[idx], vl = ql[idx];
            STS128(sb + A_QHI + sw, vh);
            STS128(sb + A_QLO + sw, vl);
        }
    }
    __syncthreads();

    uint32_t qh[4][4], qlr[4][4];
    {
        int arow = (w << 4) + (l & 7) + (((l >> 3) & 1) << 3);
        uint32_t rb = sb + (uint32_t)arow * 128u;
#pragma unroll
        for (int kk = 0; kk < 4; kk++) {
            int u = (kk << 1) + (l >> 4);
            uint32_t sw = (uint32_t)((u ^ (arow & 7)) << 4);
            ldsm4(qh[kk],  rb + A_QHI + sw);
            ldsm4(qlr[kk], rb + A_QLO + sw);
        }
    }

    float m0 = -3.0e38f, m1 = -3.0e38f, ls0 = 0.f, ls1 = 0.f;
    float o[8][4];
#pragma unroll
    for (int i = 0; i < 8; i++)
#pragma unroll
        for (int j = 0; j < 4; j++) o[i][j] = 0.f;

    const int kend  = q0 + 128;
    const int wrow0 = q0 + (w << 4);
    const int brow  = l & 7;
    const int bu    = l >> 3;

    int it = 0;
    for (int ks = 0; ks < kend; ks += 64, it++) {
        if (ks + 64 < kend) {
            stage_kv_async(sb + A_KV0 + (uint32_t)((it + 1) & 1) * 32768u,
                           b, ks + 64, tid);
            CP_COMMIT();
            CP_WAIT(1);
        } else {
            CP_WAIT(0);
        }
        __syncthreads();

        const uint32_t kvb = sb + A_KV0 + (uint32_t)(it & 1) * 32768u;

        if (ks <= wrow0 + 15) {
            float sc[8][4];
#pragma unroll
            for (int nt = 0; nt < 8; nt++) {
                int row = (nt << 3) + brow;
                uint32_t rb = kvb + (uint32_t)row * 128u;
                uint32_t s0 = (uint32_t)((bu       ^ (row & 7)) << 4);
                uint32_t s1 = (uint32_t)(((4 + bu) ^ (row & 7)) << 4);
                uint32_t kh8[8], kl8[8];
                ldsm4(kh8,     rb + A_KHI + s0);
                ldsm4(kh8 + 4, rb + A_KHI + s1);
                ldsm4(kl8,     rb + A_KLO + s0);
                ldsm4(kl8 + 4, rb + A_KLO + s1);
#pragma unroll
                for (int j = 0; j < 4; j++) sc[nt][j] = 0.f;
#pragma unroll
                for (int s = 0; s < 4; s++) {
                    mma16816(sc[nt], qh[s],  kh8[2 * s], kh8[2 * s + 1]);
                    mma16816(sc[nt], qh[s],  kl8[2 * s], kl8[2 * s + 1]);
                    mma16816(sc[nt], qlr[s], kh8[2 * s], kh8[2 * s + 1]);
                }
            }

            const int R0 = wrow0 + (l >> 2);
            if (ks + 64 > wrow0) {
                int colb = ks + ((l & 3) << 1);
#pragma unroll
                for (int nt = 0; nt < 8; nt++) {
                    int c0 = colb + (nt << 3);
                    if (c0     > R0)     sc[nt][0] = -3.0e38f;
                    if (c0 + 1 > R0)     sc[nt][1] = -3.0e38f;
                    if (c0     > R0 + 8) sc[nt][2] = -3.0e38f;
                    if (c0 + 1 > R0 + 8) sc[nt][3] = -3.0e38f;
                }
            }

            float tm0 = -3.0e38f, tm1 = -3.0e38f;
#pragma unroll
            for (int nt = 0; nt < 8; nt++) {
                tm0 = fmaxf(tm0, fmaxf(sc[nt][0], sc[nt][1]));
                tm1 = fmaxf(tm1, fmaxf(sc[nt][2], sc[nt][3]));
            }
            tm0 = fmaxf(tm0, __shfl_xor_sync(0xffffffffu, tm0, 1));
            tm0 = fmaxf(tm0, __shfl_xor_sync(0xffffffffu, tm0, 2));
            tm1 = fmaxf(tm1, __shfl_xor_sync(0xffffffffu, tm1, 1));
            tm1 = fmaxf(tm1, __shfl_xor_sync(0xffffffffu, tm1, 2));
            float mn0 = fmaxf(m0, tm0), mn1 = fmaxf(m1, tm1);
            float c0 = __expf(m0 - mn0), c1 = __expf(m1 - mn1);

            float ps0 = 0.f, ps1 = 0.f;
            uint32_t phi[4][4], plo[4][4];
#pragma unroll
            for (int s = 0; s < 4; s++) {
#pragma unroll
                for (int h = 0; h < 2; h++) {
                    int nt = 2 * s + h;
                    float p0 = __expf(sc[nt][0] - mn0);
                    float p1 = __expf(sc[nt][1] - mn0);
                    float p2 = __expf(sc[nt][2] - mn1);
                    float p3 = __expf(sc[nt][3] - mn1);
                    ps0 += p0 + p1;
                    ps1 += p2 + p3;
                    split2(p0, p1, phi[s][2 * h],     plo[s][2 * h]);
                    split2(p2, p3, phi[s][2 * h + 1], plo[s][2 * h + 1]);
                }
            }
            ps0 += __shfl_xor_sync(0xffffffffu, ps0, 1);
            ps0 += __shfl_xor_sync(0xffffffffu, ps0, 2);
            ps1 += __shfl_xor_sync(0xffffffffu, ps1, 1);
            ps1 += __shfl_xor_sync(0xffffffffu, ps1, 2);
            ls0 = ls0 * c0 + ps0;
            ls1 = ls1 * c1 + ps1;
            m0 = mn0; m1 = mn1;

#pragma unroll
            for (int nt = 0; nt < 8; nt++) {
                o[nt][0] *= c0; o[nt][1] *= c0;
                o[nt][2] *= c1; o[nt][3] *= c1;
            }
#pragma unroll
            for (int nt = 0; nt < 8; nt++) {
                int row = (nt << 3) + brow;
                uint32_t rb = kvb + (uint32_t)row * 128u;
                uint32_t s0 = (uint32_t)((bu       ^ (row & 7)) << 4);
                uint32_t s1 = (uint32_t)(((4 + bu) ^ (row & 7)) << 4);
                uint32_t vh8[8], vl8[8];
                ldsm4(vh8,     rb + A_VHI + s0);
                ldsm4(vh8 + 4, rb + A_VHI + s1);
                ldsm4(vl8,     rb + A_VLO + s0);
                ldsm4(vl8 + 4, rb + A_VLO + s1);
#pragma unroll
                for (int s = 0; s < 4; s++) {
                    mma16816(o[nt], phi[s], vh8[2 * s], vh8[2 * s + 1]);
                    mma16816(o[nt], phi[s], vl8[2 * s], vl8[2 * s + 1]);
                    mma16816(o[nt], plo[s], vh8[2 * s], vh8[2 * s + 1]);
                }
            }
        }
        __syncthreads();
    }

    const float inv0 = 1.f / ls0, inv1 = 1.f / ls1;
    const int R0g = q0 + (w << 4) + (l >> 2);
    float* o0p = out + (((size_t)(b * Tn + R0g)) << 6) + ((l & 3) << 1);
    float* o1p = o0p + (8 << 6);
#pragma unroll
    for (int nt = 0; nt < 8; nt++) {
        *(float2*)(o0p + (nt << 3)) = make_float2(o[nt][0] * inv0, o[nt][1] * inv0);
        *(float2*)(o1p + (nt << 3)) = make_float2(o[nt][2] * inv1, o[nt][3] * inv1);
    }
}

// ===================== launch =====================
extern "C" void kernel_launch(void* const* d_in, const int* in_sizes, int n_in,
                              void* d_out, int out_size)
{
    const float* x  = (const float*)d_in[0];
    const float* WQ = (const float*)d_in[1];
    const float* WK = (const float*)d_in[2];
    const float* WV = (const float*)d_in[3];
    float* out = (float*)d_out;

    cudaFuncSetAttribute(proj_tc_kernel,
                         cudaFuncAttributeMaxDynamicSharedMemorySize, PROJ_SMEM);
    cudaFuncSetAttribute(attn_kernel,
                         cudaFuncAttributeMaxDynamicSharedMemorySize, ATTN_SMEM);

    prep_w<<<192, 128>>>(WQ, WK, WV);
    proj_tc_kernel<<<(Bn * Tn) / 128, 256, PROJ_SMEM>>>(x);
    attn_kernel<<<256, 256, ATTN_SMEM>>>(out);
}